// round 12
// baseline (speedup 1.0000x reference)
#include <cuda_runtime.h>
#include <cuda_bf16.h>
#include <math.h>
#include <stdint.h>

#define NB 16
#define CDIM 256
#define TDIM 1024
#define CTXL 48
#define TGTR 1072      // CTXL + TDIM
#define FFD 1024
#define NLAYER 4
#define MQ (NB * TGTR)   // 17152
#define MT (NB * TDIM)   // 16384

// ---------------- scratch (static device globals — no allocation) ----------------
__device__ float g_tgt[MQ * CDIM];
__device__ float g_qkv[MQ * 3 * CDIM];
__device__ float g_x1 [MT * CDIM];

__device__ unsigned short g_tgth[MQ * CDIM], g_tgtl[MQ * CDIM];
__device__ unsigned short g_atth[MT * CDIM], g_attl[MT * CDIM];
__device__ unsigned short g_x1h [MT * CDIM], g_x1l [MT * CDIM];
__device__ unsigned short g_ffh [MT * FFD],  g_ffl [MT * FFD];

__device__ unsigned short g_wqh[NLAYER*3*CDIM*CDIM], g_wql[NLAYER*3*CDIM*CDIM];
__device__ unsigned short g_woh[NLAYER*CDIM*CDIM],   g_wol[NLAYER*CDIM*CDIM];
__device__ unsigned short g_w1h[NLAYER*FFD*CDIM],    g_w1l[NLAYER*FFD*CDIM];
__device__ unsigned short g_w2h[NLAYER*CDIM*FFD],    g_w2l[NLAYER*CDIM*FFD];

// ---------------- helpers ----------------
__device__ __forceinline__ void bsplit(float x, unsigned short& h, unsigned short& l) {
    __nv_bfloat16 hb = __float2bfloat16(x);
    float r = x - __bfloat162float(hb);
    __nv_bfloat16 lb = __float2bfloat16(r);
    h = *(unsigned short*)&hb; l = *(unsigned short*)&lb;
}

__device__ __forceinline__ void mma16816(float* d, const unsigned* a, unsigned b0, unsigned b1) {
    asm volatile(
        "mma.sync.aligned.m16n8k16.row.col.f32.bf16.bf16.f32 "
        "{%0,%1,%2,%3}, {%4,%5,%6,%7}, {%8,%9}, {%0,%1,%2,%3};"
        : "+f"(d[0]), "+f"(d[1]), "+f"(d[2]), "+f"(d[3])
        : "r"(a[0]), "r"(a[1]), "r"(a[2]), "r"(a[3]), "r"(b0), "r"(b1));
}

// ---------------- depthwise causal conv (Le=32), fused bf16 split ----------------
__global__ void conv_kernel(const float* __restrict__ x, const float* __restrict__ emb) {
    int b = blockIdx.y;
    int t0 = blockIdx.x * 16;
    int c = threadIdx.x;
    float f[32];
#pragma unroll
    for (int l = 0; l < 32; l++)
        f[l] = 0.5f * (emb[((b * 2 + 0) * CDIM + c) * 32 + l] +
                       emb[((b * 2 + 1) * CDIM + c) * 32 + l]);
    float xv[47];
    const float* xr = x + ((long)(b * CDIM + c)) * TDIM;
#pragma unroll
    for (int l = 0; l < 47; l++) {
        int t = t0 - 31 + l;
        xv[l] = (t >= 0) ? xr[t] : 0.0f;
    }
#pragma unroll
    for (int tt = 0; tt < 16; tt++) {
        float s = 0.0f;
#pragma unroll
        for (int l = 0; l < 32; l++) s += xv[tt + l] * f[l];
        long idx = ((long)(b * TGTR + CTXL + t0 + tt)) * CDIM + c;
        g_tgt[idx] = s;
        unsigned short h, lo; bsplit(s, h, lo);
        g_tgth[idx] = h; g_tgtl[idx] = lo;
    }
}

// ---------------- per-layer prep: ctx snapshot + ctx load (+ split) ----------------
__global__ void prep_kernel(const float* __restrict__ ctx_in, float* __restrict__ ctx_out,
                            int layer, int write_ctx) {
    int b = blockIdx.x;
    long snap_base = ((long)(b * TGTR + TDIM)) * CDIM;
    long tgt_base  = ((long)(b * TGTR)) * CDIM;
    long io_base   = ((long)((b * NLAYER + layer) * CTXL)) * CDIM;
    for (int i = threadIdx.x; i < CTXL * CDIM; i += blockDim.x) {
        if (write_ctx) ctx_out[io_base + i] = g_tgt[snap_base + i];
        float v = ctx_in[io_base + i];
        g_tgt[tgt_base + i] = v;
        unsigned short h, lo; bsplit(v, h, lo);
        g_tgth[tgt_base + i] = h; g_tgtl[tgt_base + i] = lo;
    }
}

// ---------------- weight fp32 -> bf16 hi/lo (once per launch) ----------------
__global__ void wconv_kernel(const float* __restrict__ src, unsigned short* __restrict__ h,
                             unsigned short* __restrict__ l, int n) {
    int stride = gridDim.x * blockDim.x;
    for (int i = blockIdx.x * blockDim.x + threadIdx.x; i < n; i += stride) {
        unsigned short hh, ll; bsplit(src[i], hh, ll);
        h[i] = hh; l[i] = ll;
    }
}

// ---------------- GEMM via mma.sync bf16 3-split ----------------
// Pre-split operands, permuted smem layout (fragment pairs adjacent -> LDS.64),
// double-buffered smem (one sync per k-tile).
// out[M,N] = A[M,K] @ W[N,K]^T + bias.
// EPI: 0 = +bias -> f32 ; 1 = +bias + res -> f32 ; 2 = +bias, relu -> bf16 hi/lo
// Dynamic smem: 2 bufs x (Ah,Al,Bh,Bl) x [128][12] u32 = 49152 B.
#define GS_BUF 6144   // u32 per buffer
#define GS_AL  1536
#define GS_BH  3072
#define GS_BL  4608

template<int EPI>
__global__ void __launch_bounds__(256, 2) gemm_kernel(
    const unsigned* __restrict__ Ah, const unsigned* __restrict__ Al,
    const unsigned* __restrict__ Wh, const unsigned* __restrict__ Wl,
    const float* __restrict__ bias, const float* __restrict__ res,
    float* __restrict__ outf, unsigned short* __restrict__ outh, unsigned short* __restrict__ outl,
    int K, int N, int res_remap, int out_remap)
{
    extern __shared__ unsigned dsm[];

    int tid = threadIdx.x;
    int lane = tid & 31;
    int wid = tid >> 5;
    int wm = wid >> 1;
    int wn = wid & 1;
    int g = lane >> 2, t = lane & 3;
    int m0 = blockIdx.y * 128, n0 = blockIdx.x * 128;

    float acc[2][8][4];
#pragma unroll
    for (int i = 0; i < 2; i++)
#pragma unroll
        for (int j = 0; j < 8; j++)
#pragma unroll
            for (int c = 0; c < 4; c++) acc[i][j][c] = 0.0f;

    int Ku = K >> 1;
    int srow = tid >> 1;            // 0..127
    int uc   = (tid & 1) * 4;       // source u32 col 0..3 or 4..7
    const unsigned* Aph = Ah + (long)(m0 + srow) * Ku + uc;
    const unsigned* Apl = Al + (long)(m0 + srow) * Ku + uc;
    const unsigned* Wph = Wh + (long)(n0 + srow) * Ku + uc;
    const unsigned* Wpl = Wl + (long)(n0 + srow) * Ku + uc;

    // permuted store base: col c -> (c&3)*2 + (c>>2); for this thread p = (tid&1) + 2*j
    unsigned* sbase = dsm + srow * 12 + (tid & 1);

    uint4 ah4 = *(const uint4*)Aph;
    uint4 al4 = *(const uint4*)Apl;
    uint4 wh4 = *(const uint4*)Wph;
    uint4 wl4 = *(const uint4*)Wpl;

    // prologue: stage tile 0 -> buf 0
    {
        unsigned* p0 = sbase;
        p0[0] = ah4.x; p0[2] = ah4.y; p0[4] = ah4.z; p0[6] = ah4.w;
        p0[GS_AL + 0] = al4.x; p0[GS_AL + 2] = al4.y; p0[GS_AL + 4] = al4.z; p0[GS_AL + 6] = al4.w;
        p0[GS_BH + 0] = wh4.x; p0[GS_BH + 2] = wh4.y; p0[GS_BH + 4] = wh4.z; p0[GS_BH + 6] = wh4.w;
        p0[GS_BL + 0] = wl4.x; p0[GS_BL + 2] = wl4.y; p0[GS_BL + 4] = wl4.z; p0[GS_BL + 6] = wl4.w;
    }
    __syncthreads();

    int KT = K >> 4;
    for (int kt = 0; kt < KT; kt++) {
        int buf = kt & 1;
        bool more = (kt + 1 < KT);
        if (more) {
            int off = (kt + 1) << 3;
            ah4 = *(const uint4*)(Aph + off);
            al4 = *(const uint4*)(Apl + off);
            wh4 = *(const uint4*)(Wph + off);
            wl4 = *(const uint4*)(Wpl + off);
        }

        const unsigned* bp = dsm + buf * GS_BUF;
        unsigned afh[2][4], afl[2][4];
#pragma unroll
        for (int tm = 0; tm < 2; tm++) {
            int r = wm * 32 + tm * 16 + g;
            uint2 h02 = *(const uint2*)(bp + r * 12 + 2 * t);
            uint2 h13 = *(const uint2*)(bp + (r + 8) * 12 + 2 * t);
            afh[tm][0] = h02.x; afh[tm][1] = h13.x; afh[tm][2] = h02.y; afh[tm][3] = h13.y;
            uint2 l02 = *(const uint2*)(bp + GS_AL + r * 12 + 2 * t);
            uint2 l13 = *(const uint2*)(bp + GS_AL + (r + 8) * 12 + 2 * t);
            afl[tm][0] = l02.x; afl[tm][1] = l13.x; afl[tm][2] = l02.y; afl[tm][3] = l13.y;
        }
#pragma unroll
        for (int tn = 0; tn < 8; tn++) {
            int nc = wn * 64 + tn * 8 + g;
            uint2 bh = *(const uint2*)(bp + GS_BH + nc * 12 + 2 * t);
            uint2 bl = *(const uint2*)(bp + GS_BL + nc * 12 + 2 * t);
#pragma unroll
            for (int tm = 0; tm < 2; tm++) {
                mma16816(acc[tm][tn], afh[tm], bh.x, bh.y);   // hi*hi
                mma16816(acc[tm][tn], afl[tm], bh.x, bh.y);   // lo*hi
                mma16816(acc[tm][tn], afh[tm], bl.x, bl.y);   // hi*lo
            }
        }

        if (more) {
            unsigned* p1 = sbase + (buf ^ 1) * GS_BUF;
            p1[0] = ah4.x; p1[2] = ah4.y; p1[4] = ah4.z; p1[6] = ah4.w;
            p1[GS_AL + 0] = al4.x; p1[GS_AL + 2] = al4.y; p1[GS_AL + 4] = al4.z; p1[GS_AL + 6] = al4.w;
            p1[GS_BH + 0] = wh4.x; p1[GS_BH + 2] = wh4.y; p1[GS_BH + 4] = wh4.z; p1[GS_BH + 6] = wh4.w;
            p1[GS_BL + 0] = wl4.x; p1[GS_BL + 2] = wl4.y; p1[GS_BL + 4] = wl4.z; p1[GS_BL + 6] = wl4.w;
            __syncthreads();
        }
    }

    // epilogue: c0=(g,2t) c1=(g,2t+1) c2=(g+8,2t) c3=(g+8,2t+1)
#pragma unroll
    for (int tm = 0; tm < 2; tm++) {
#pragma unroll
        for (int tn = 0; tn < 8; tn++) {
            int col = n0 + wn * 64 + tn * 8 + 2 * t;
            float bz0 = bias[col], bz1 = bias[col + 1];
#pragma unroll
            for (int half = 0; half < 2; half++) {
                int row = m0 + wm * 32 + tm * 16 + g + half * 8;
                float v0 = acc[tm][tn][half * 2 + 0] + bz0;
                float v1 = acc[tm][tn][half * 2 + 1] + bz1;
                if (EPI == 1) {
                    long rrow = res_remap ? (row + 48 * (row >> 10) + 48) : row;
                    const float* rp = &res[rrow * CDIM + col];
                    v0 += rp[0]; v1 += rp[1];
                }
                if (EPI == 2) {
                    v0 = fmaxf(v0, 0.0f); v1 = fmaxf(v1, 0.0f);
                    unsigned short h0, l0, h1, l1;
                    bsplit(v0, h0, l0); bsplit(v1, h1, l1);
                    long oi = (long)row * (N >> 1) + (col >> 1);
                    ((unsigned*)outh)[oi] = (unsigned)h0 | ((unsigned)h1 << 16);
                    ((unsigned*)outl)[oi] = (unsigned)l0 | ((unsigned)l1 << 16);
                } else {
                    long orow = out_remap ? (row + 48 * (row >> 10) + 48) : row;
                    *(float2*)&outf[orow * (long)N + col] = make_float2(v0, v1);
                }
            }
        }
    }
}

#define GEMM_SMEM 49152

// ---------------- LayerNorm (in place) + bf16 split ----------------
__global__ void ln_kernel(float* __restrict__ buf, const float* __restrict__ g,
                          const float* __restrict__ bt,
                          unsigned short* __restrict__ oh, unsigned short* __restrict__ ol,
                          int remap) {
    int row = blockIdx.x * 8 + (threadIdx.x >> 5);
    int lane = threadIdx.x & 31;
    int br = remap ? (row + 48 * (row >> 10) + 48) : row;
    float* p = buf + ((long)br) * CDIM + lane * 8;
    float4 v0 = *(float4*)p;
    float4 v1 = *(float4*)(p + 4);
    float v[8] = {v0.x, v0.y, v0.z, v0.w, v1.x, v1.y, v1.z, v1.w};
    float s = 0.0f;
#pragma unroll
    for (int i = 0; i < 8; i++) s += v[i];
#pragma unroll
    for (int o = 16; o > 0; o >>= 1) s += __shfl_xor_sync(0xffffffffu, s, o);
    float mu = s * (1.0f / 256.0f);
    float sq = 0.0f;
#pragma unroll
    for (int i = 0; i < 8; i++) { float d = v[i] - mu; sq += d * d; }
#pragma unroll
    for (int o = 16; o > 0; o >>= 1) sq += __shfl_xor_sync(0xffffffffu, sq, o);
    float rstd = rsqrtf(sq * (1.0f / 256.0f) + 1e-5f);
#pragma unroll
    for (int i = 0; i < 8; i++) {
        int c = lane * 8 + i;
        v[i] = (v[i] - mu) * rstd * g[c] + bt[c];
    }
    *(float4*)p       = make_float4(v[0], v[1], v[2], v[3]);
    *(float4*)(p + 4) = make_float4(v[4], v[5], v[6], v[7]);
    unsigned hv[4], lv[4];
#pragma unroll
    for (int i = 0; i < 8; i += 2) {
        unsigned short h0, l0, h1, l1;
        bsplit(v[i], h0, l0); bsplit(v[i + 1], h1, l1);
        hv[i >> 1] = (unsigned)h0 | ((unsigned)h1 << 16);
        lv[i >> 1] = (unsigned)l0 | ((unsigned)l1 << 16);
    }
    unsigned* ohp = (unsigned*)oh + (long)br * 128 + lane * 4;
    unsigned* olp = (unsigned*)ol + (long)br * 128 + lane * 4;
    *(uint4*)ohp = *(uint4*)hv;
    *(uint4*)olp = *(uint4*)lv;
}

// ---------------- windowed attention, online softmax, 16-token slabs ----------------
__global__ void __launch_bounds__(128) attn_kernel() {
    __shared__ float sK[16 * 256];
    __shared__ float sV[16 * 256];
    int b = blockIdx.x >> 6, w = blockIdx.x & 63;
    int tid = threadIdx.x;
    int h = tid >> 4, qi = tid & 15;
    long rbase = (long)b * TGTR + w * 16;

    float q[32];
    const float* qp = g_qkv + (rbase + 48 + qi) * 768 + h * 32;
#pragma unroll
    for (int d = 0; d < 32; d++) q[d] = qp[d];

    float mx = -1e30f, sum = 0.0f;
    float o[32];
#pragma unroll
    for (int d = 0; d < 32; d++) o[d] = 0.0f;

    float4* sKf = (float4*)sK;
    float4* sVf = (float4*)sV;
    const float4* qkvf = (const float4*)g_qkv;

    for (int slab = 0; slab < 4; slab++) {
        __syncthreads();
#pragma unroll
        for (int i = tid; i < 1024; i += 128) {
            int jj = i >> 6, c4 = i & 63;
            long trow = rbase + slab * 16 + jj;
            sKf[i] = qkvf[trow * 192 + 64  + c4];
            sVf[i] = qkvf[trow * 192 + 128 + c4];
        }
        __syncthreads();
#pragma unroll
        for (int jj = 0; jj < 16; jj++) {
            const float* kp = sK + jj * 256 + h * 32;
            float s = 0.0f;
#pragma unroll
            for (int d = 0; d < 32; d++) s += q[d] * kp[d];
            s *= 0.17677669529663687f;
            float nm = fmaxf(mx, s);
            float corr = __expf(mx - nm);
            float p = __expf(s - nm);
            sum = sum * corr + p;
            const float* vp = sV + jj * 256 + h * 32;
#pragma unroll
            for (int d = 0; d < 32; d++) o[d] = o[d] * corr + p * vp[d];
            mx = nm;
        }
    }
    float inv = 1.0f / sum;
    long oidx = ((long)(b * TDIM + w * 16 + qi)) * CDIM + h * 32;
    unsigned hv[16], lv[16];
#pragma unroll
    for (int d = 0; d < 32; d += 2) {
        unsigned short h0, l0, h1, l1;
        bsplit(o[d] * inv, h0, l0); bsplit(o[d + 1] * inv, h1, l1);
        hv[d >> 1] = (unsigned)h0 | ((unsigned)h1 << 16);
        lv[d >> 1] = (unsigned)l0 | ((unsigned)l1 << 16);
    }
    unsigned* ohp = (unsigned*)g_atth + (oidx >> 1);
    unsigned* olp = (unsigned*)g_attl + (oidx >> 1);
#pragma unroll
    for (int j = 0; j < 4; j++) {
        ((uint4*)ohp)[j] = ((uint4*)hv)[j];
        ((uint4*)olp)[j] = ((uint4*)lv)[j];
    }
}

// ---------------- final transpose: g_tgt[b][48+t][c] -> out[b][c][t] ----------------
__global__ void out_transpose(float* __restrict__ outp) {
    __shared__ float tile[32][33];
    int b = blockIdx.z;
    int t0 = blockIdx.x * 32, c0 = blockIdx.y * 32;
    int tx = threadIdx.x, ty = threadIdx.y;
#pragma unroll
    for (int i = 0; i < 32; i += 8)
        tile[ty + i][tx] = g_tgt[((long)(b * TGTR + CTXL + t0 + ty + i)) * CDIM + c0 + tx];
    __syncthreads();
#pragma unroll
    for (int i = 0; i < 32; i += 8)
        outp[((long)(b * CDIM + c0 + ty + i)) * TDIM + t0 + tx] = tile[tx][ty + i];
}

extern "C" void kernel_launch(void* const* d_in, const int* in_sizes, int n_in,
                              void* d_out, int out_size) {
    const float* x      = (const float*)d_in[0];
    const float* emb    = (const float*)d_in[1];
    const float* ctx_in = (const float*)d_in[2];
    const float* Wqkv   = (const float*)d_in[3];
    const float* bqkv   = (const float*)d_in[4];
    const float* Wo     = (const float*)d_in[5];
    const float* bo     = (const float*)d_in[6];
    const float* W1     = (const float*)d_in[7];
    const float* b1     = (const float*)d_in[8];
    const float* W2     = (const float*)d_in[9];
    const float* b2     = (const float*)d_in[10];
    const float* ln1g   = (const float*)d_in[11];
    const float* ln1b   = (const float*)d_in[12];
    const float* ln3g   = (const float*)d_in[13];
    const float* ln3b   = (const float*)d_in[14];

    float* outp = (float*)d_out;
    float* ctx_out = outp + (long)NB * CDIM * TDIM;
    int write_ctx = (out_size >= NB * CDIM * TDIM + NB * NLAYER * CTXL * CDIM) ? 1 : 0;

    float *tgt, *qkv, *x1;
    unsigned short *tgth, *tgtl, *atth, *attl, *x1h, *x1l, *ffh, *ffl;
    unsigned short *wqh, *wql, *woh, *wol, *w1h, *w1l, *w2h, *w2l;
    cudaGetSymbolAddress((void**)&tgt,  g_tgt);
    cudaGetSymbolAddress((void**)&qkv,  g_qkv);
    cudaGetSymbolAddress((void**)&x1,   g_x1);
    cudaGetSymbolAddress((void**)&tgth, g_tgth); cudaGetSymbolAddress((void**)&tgtl, g_tgtl);
    cudaGetSymbolAddress((void**)&atth, g_atth); cudaGetSymbolAddress((void**)&attl, g_attl);
    cudaGetSymbolAddress((void**)&x1h,  g_x1h);  cudaGetSymbolAddress((void**)&x1l,  g_x1l);
    cudaGetSymbolAddress((void**)&ffh,  g_ffh);  cudaGetSymbolAddress((void**)&ffl,  g_ffl);
    cudaGetSymbolAddress((void**)&wqh,  g_wqh);  cudaGetSymbolAddress((void**)&wql,  g_wql);
    cudaGetSymbolAddress((void**)&woh,  g_woh);  cudaGetSymbolAddress((void**)&wol,  g_wol);
    cudaGetSymbolAddress((void**)&w1h,  g_w1h);  cudaGetSymbolAddress((void**)&w1l,  g_w1l);
    cudaGetSymbolAddress((void**)&w2h,  g_w2h);  cudaGetSymbolAddress((void**)&w2l,  g_w2l);

    cudaFuncSetAttribute(gemm_kernel<0>, cudaFuncAttributeMaxDynamicSharedMemorySize, GEMM_SMEM);
    cudaFuncSetAttribute(gemm_kernel<1>, cudaFuncAttributeMaxDynamicSharedMemorySize, GEMM_SMEM);
    cudaFuncSetAttribute(gemm_kernel<2>, cudaFuncAttributeMaxDynamicSharedMemorySize, GEMM_SMEM);

    // weight pre-split (once per launch)
    wconv_kernel<<<512, 256>>>(Wqkv, wqh, wql, NLAYER * 3 * CDIM * CDIM);
    wconv_kernel<<<256, 256>>>(Wo,   woh, wol, NLAYER * CDIM * CDIM);
    wconv_kernel<<<512, 256>>>(W1,   w1h, w1l, NLAYER * FFD * CDIM);
    wconv_kernel<<<512, 256>>>(W2,   w2h, w2l, NLAYER * CDIM * FFD);

    conv_kernel<<<dim3(64, 16), 256>>>(x, emb);

    for (int l = 0; l < NLAYER; l++) {
        prep_kernel<<<NB, 256>>>(ctx_in, ctx_out, l, write_ctx);
        // QKV: M=17152, N=768, K=256 -> qkv f32
        gemm_kernel<0><<<dim3(6, 134), 256, GEMM_SMEM>>>(
            (unsigned*)tgth, (unsigned*)tgtl,
            (unsigned*)(wqh + (long)l * 3 * CDIM * CDIM), (unsigned*)(wql + (long)l * 3 * CDIM * CDIM),
            bqkv + l * 768, nullptr, qkv, nullptr, nullptr, 256, 768, 0, 0);
        attn_kernel<<<NB * 64, 128>>>();
        // Wo: M=16384, N=256, K=256, +res(tgt remap) -> x1 f32
        gemm_kernel<1><<<dim3(2, 128), 256, GEMM_SMEM>>>(
            (unsigned*)atth, (unsigned*)attl,
            (unsigned*)(woh + (long)l * CDIM * CDIM), (unsigned*)(wol + (long)l * CDIM * CDIM),
            bo + l * 256, tgt, x1, nullptr, nullptr, 256, 256, 1, 0);
        ln_kernel<<<2048, 256>>>(x1, ln1g + l * 256, ln1b + l * 256, x1h, x1l, 0);
        // FF1: M=16384, N=1024, K=256, relu -> ff hi/lo
        gemm_kernel<2><<<dim3(8, 128), 256, GEMM_SMEM>>>(
            (unsigned*)x1h, (unsigned*)x1l,
            (unsigned*)(w1h + (long)l * FFD * CDIM), (unsigned*)(w1l + (long)l * FFD * CDIM),
            b1 + l * 1024, nullptr, nullptr, ffh, ffl, 256, 1024, 0, 0);
        // FF2: M=16384, N=256, K=1024, +res(x1) -> tgt f32 (remap rows)
        gemm_kernel<1><<<dim3(2, 128), 256, GEMM_SMEM>>>(
            (unsigned*)ffh, (unsigned*)ffl,
            (unsigned*)(w2h + (long)l * CDIM * FFD), (unsigned*)(w2l + (long)l * CDIM * FFD),
            b2 + l * 256, x1, tgt, nullptr, nullptr, 1024, 256, 0, 1);
        ln_kernel<<<2048, 256>>>(tgt, ln3g + l * 256, ln3b + l * 256, tgth, tgtl, 1);
    }

    out_transpose<<<dim3(32, 8, 16), dim3(32, 8)>>>(outp);
}

// round 15
// speedup vs baseline: 1.0818x; 1.0818x over previous
#include <cuda_runtime.h>
#include <cuda_bf16.h>
#include <math.h>
#include <stdint.h>

#define NB 16
#define CDIM 256
#define TDIM 1024
#define CTXL 48
#define TGTR 1072      // CTXL + TDIM
#define FFD 1024
#define NLAYER 4
#define MQ (NB * TGTR)   // 17152
#define MT (NB * TDIM)   // 16384

// ---------------- scratch (static device globals — no allocation) ----------------
__device__ float g_tgt[MQ * CDIM];
__device__ float g_qkv[MQ * 3 * CDIM];
__device__ float g_x1 [MT * CDIM];

__device__ unsigned short g_tgth[MQ * CDIM], g_tgtl[MQ * CDIM];
__device__ unsigned short g_atth[MT * CDIM], g_attl[MT * CDIM];
__device__ unsigned short g_x1h [MT * CDIM], g_x1l [MT * CDIM];
__device__ unsigned short g_ffh [MT * FFD],  g_ffl [MT * FFD];

__device__ unsigned short g_wqh[NLAYER*3*CDIM*CDIM], g_wql[NLAYER*3*CDIM*CDIM];
__device__ unsigned short g_woh[NLAYER*CDIM*CDIM],   g_wol[NLAYER*CDIM*CDIM];
__device__ unsigned short g_w1h[NLAYER*FFD*CDIM],    g_w1l[NLAYER*FFD*CDIM];
__device__ unsigned short g_w2h[NLAYER*CDIM*FFD],    g_w2l[NLAYER*CDIM*FFD];

// ---------------- helpers ----------------
__device__ __forceinline__ void bsplit(float x, unsigned short& h, unsigned short& l) {
    __nv_bfloat16 hb = __float2bfloat16(x);
    float r = x - __bfloat162float(hb);
    __nv_bfloat16 lb = __float2bfloat16(r);
    h = *(unsigned short*)&hb; l = *(unsigned short*)&lb;
}

__device__ __forceinline__ void mma16816(float* d, const unsigned* a, unsigned b0, unsigned b1) {
    asm volatile(
        "mma.sync.aligned.m16n8k16.row.col.f32.bf16.bf16.f32 "
        "{%0,%1,%2,%3}, {%4,%5,%6,%7}, {%8,%9}, {%0,%1,%2,%3};"
        : "+f"(d[0]), "+f"(d[1]), "+f"(d[2]), "+f"(d[3])
        : "r"(a[0]), "r"(a[1]), "r"(a[2]), "r"(a[3]), "r"(b0), "r"(b1));
}

// ---------------- depthwise causal conv (Le=32), fused bf16 split ----------------
__global__ void conv_kernel(const float* __restrict__ x, const float* __restrict__ emb) {
    int b = blockIdx.y;
    int t0 = blockIdx.x * 16;
    int c = threadIdx.x;
    float f[32];
#pragma unroll
    for (int l = 0; l < 32; l++)
        f[l] = 0.5f * (emb[((b * 2 + 0) * CDIM + c) * 32 + l] +
                       emb[((b * 2 + 1) * CDIM + c) * 32 + l]);
    float xv[47];
    const float* xr = x + ((long)(b * CDIM + c)) * TDIM;
#pragma unroll
    for (int l = 0; l < 47; l++) {
        int t = t0 - 31 + l;
        xv[l] = (t >= 0) ? xr[t] : 0.0f;
    }
#pragma unroll
    for (int tt = 0; tt < 16; tt++) {
        float s = 0.0f;
#pragma unroll
        for (int l = 0; l < 32; l++) s += xv[tt + l] * f[l];
        long idx = ((long)(b * TGTR + CTXL + t0 + tt)) * CDIM + c;
        g_tgt[idx] = s;
        unsigned short h, lo; bsplit(s, h, lo);
        g_tgth[idx] = h; g_tgtl[idx] = lo;
    }
}

// ---------------- per-layer prep: ctx snapshot + ctx load (+ split) ----------------
__global__ void prep_kernel(const float* __restrict__ ctx_in, float* __restrict__ ctx_out,
                            int layer, int write_ctx) {
    int b = blockIdx.x;
    long snap_base = ((long)(b * TGTR + TDIM)) * CDIM;
    long tgt_base  = ((long)(b * TGTR)) * CDIM;
    long io_base   = ((long)((b * NLAYER + layer) * CTXL)) * CDIM;
    for (int i = threadIdx.x; i < CTXL * CDIM; i += blockDim.x) {
        if (write_ctx) ctx_out[io_base + i] = g_tgt[snap_base + i];
        float v = ctx_in[io_base + i];
        g_tgt[tgt_base + i] = v;
        unsigned short h, lo; bsplit(v, h, lo);
        g_tgth[tgt_base + i] = h; g_tgtl[tgt_base + i] = lo;
    }
}

// ---------------- weight fp32 -> bf16 hi/lo (once per launch) ----------------
__global__ void wconv_kernel(const float* __restrict__ src, unsigned short* __restrict__ h,
                             unsigned short* __restrict__ l, int n) {
    int stride = gridDim.x * blockDim.x;
    for (int i = blockIdx.x * blockDim.x + threadIdx.x; i < n; i += stride) {
        unsigned short hh, ll; bsplit(src[i], hh, ll);
        h[i] = hh; l[i] = ll;
    }
}

// ---------------- GEMM via mma.sync bf16 3-split, pre-split operands (R11 design) ----
// out[M,N] = A[M,K] @ W[N,K]^T + bias.
// EPI: 0 = +bias -> f32 ; 1 = +bias + res -> f32 ; 2 = +bias, relu -> bf16 hi/lo
// A,W given as u32 arrays of packed bf16 pairs: [row][K/2].
// Block 128x128, 8 warps (4m x 2n), warp tile 32x64, k-step 16.
template<int EPI>
__global__ void __launch_bounds__(256, 2) gemm_kernel(
    const unsigned* __restrict__ Ah, const unsigned* __restrict__ Al,
    const unsigned* __restrict__ Wh, const unsigned* __restrict__ Wl,
    const float* __restrict__ bias, const float* __restrict__ res,
    float* __restrict__ outf, unsigned short* __restrict__ outh, unsigned short* __restrict__ outl,
    int K, int N, int res_remap, int out_remap)
{
    __shared__ unsigned sA[2][128][12];   // [hi/lo][row][8 u32 used, stride 12]
    __shared__ unsigned sB[2][128][12];

    int tid = threadIdx.x;
    int lane = tid & 31;
    int wid = tid >> 5;
    int wm = wid >> 1;
    int wn = wid & 1;
    int g = lane >> 2, t = lane & 3;
    int m0 = blockIdx.y * 128, n0 = blockIdx.x * 128;

    float acc[2][8][4];
#pragma unroll
    for (int i = 0; i < 2; i++)
#pragma unroll
        for (int j = 0; j < 8; j++)
#pragma unroll
            for (int c = 0; c < 4; c++) acc[i][j][c] = 0.0f;

    int Ku = K >> 1;
    int srow = tid >> 1;            // 0..127
    int uc   = (tid & 1) * 4;       // u32 col 0..3 or 4..7
    const unsigned* Aph = Ah + (long)(m0 + srow) * Ku + uc;
    const unsigned* Apl = Al + (long)(m0 + srow) * Ku + uc;
    const unsigned* Wph = Wh + (long)(n0 + srow) * Ku + uc;
    const unsigned* Wpl = Wl + (long)(n0 + srow) * Ku + uc;

    uint4 ah4 = *(const uint4*)Aph;
    uint4 al4 = *(const uint4*)Apl;
    uint4 wh4 = *(const uint4*)Wph;
    uint4 wl4 = *(const uint4*)Wpl;

    int KT = K >> 4;
    for (int kt = 0; kt < KT; kt++) {
        // stage current k-tile (pure copies)
        sA[0][srow][uc + 0] = ah4.x; sA[0][srow][uc + 1] = ah4.y;
        sA[0][srow][uc + 2] = ah4.z; sA[0][srow][uc + 3] = ah4.w;
        sA[1][srow][uc + 0] = al4.x; sA[1][srow][uc + 1] = al4.y;
        sA[1][srow][uc + 2] = al4.z; sA[1][srow][uc + 3] = al4.w;
        sB[0][srow][uc + 0] = wh4.x; sB[0][srow][uc + 1] = wh4.y;
        sB[0][srow][uc + 2] = wh4.z; sB[0][srow][uc + 3] = wh4.w;
        sB[1][srow][uc + 0] = wl4.x; sB[1][srow][uc + 1] = wl4.y;
        sB[1][srow][uc + 2] = wl4.z; sB[1][srow][uc + 3] = wl4.w;
        __syncthreads();

        bool more = (kt + 1 < KT);
        if (more) {
            int off = (kt + 1) << 3;
            ah4 = *(const uint4*)(Aph + off);
            al4 = *(const uint4*)(Apl + off);
            wh4 = *(const uint4*)(Wph + off);
            wl4 = *(const uint4*)(Wpl + off);
        }

        unsigned afh[2][4], afl[2][4];
#pragma unroll
        for (int tm = 0; tm < 2; tm++) {
            int r = wm * 32 + tm * 16 + g;
            afh[tm][0] = sA[0][r][t];     afh[tm][1] = sA[0][r + 8][t];
            afh[tm][2] = sA[0][r][4 + t]; afh[tm][3] = sA[0][r + 8][4 + t];
            afl[tm][0] = sA[1][r][t];     afl[tm][1] = sA[1][r + 8][t];
            afl[tm][2] = sA[1][r][4 + t]; afl[tm][3] = sA[1][r + 8][4 + t];
        }
#pragma unroll
        for (int tn = 0; tn < 8; tn++) {
            int nc = wn * 64 + tn * 8 + g;
            unsigned b0h = sB[0][nc][t], b1h = sB[0][nc][4 + t];
            unsigned b0l = sB[1][nc][t], b1l = sB[1][nc][4 + t];
#pragma unroll
            for (int tm = 0; tm < 2; tm++) {
                mma16816(acc[tm][tn], afh[tm], b0h, b1h);   // hi*hi
                mma16816(acc[tm][tn], afl[tm], b0h, b1h);   // lo*hi
                mma16816(acc[tm][tn], afh[tm], b0l, b1l);   // hi*lo
            }
        }
        __syncthreads();
    }

    // epilogue: c0=(g,2t) c1=(g,2t+1) c2=(g+8,2t) c3=(g+8,2t+1)
#pragma unroll
    for (int tm = 0; tm < 2; tm++) {
#pragma unroll
        for (int tn = 0; tn < 8; tn++) {
            int col = n0 + wn * 64 + tn * 8 + 2 * t;
            float bz0 = bias[col], bz1 = bias[col + 1];
#pragma unroll
            for (int half = 0; half < 2; half++) {
                int row = m0 + wm * 32 + tm * 16 + g + half * 8;
                float v0 = acc[tm][tn][half * 2 + 0] + bz0;
                float v1 = acc[tm][tn][half * 2 + 1] + bz1;
                if (EPI == 1) {
                    long rrow = res_remap ? (row + 48 * (row >> 10) + 48) : row;
                    const float* rp = &res[rrow * CDIM + col];
                    v0 += rp[0]; v1 += rp[1];
                }
                if (EPI == 2) {
                    v0 = fmaxf(v0, 0.0f); v1 = fmaxf(v1, 0.0f);
                    unsigned short h0, l0, h1, l1;
                    bsplit(v0, h0, l0); bsplit(v1, h1, l1);
                    long oi = (long)row * (N >> 1) + (col >> 1);
                    ((unsigned*)outh)[oi] = (unsigned)h0 | ((unsigned)h1 << 16);
                    ((unsigned*)outl)[oi] = (unsigned)l0 | ((unsigned)l1 << 16);
                } else {
                    long orow = out_remap ? (row + 48 * (row >> 10) + 48) : row;
                    *(float2*)&outf[orow * (long)N + col] = make_float2(v0, v1);
                }
            }
        }
    }
}

// ---------------- LayerNorm (in place) + bf16 split ----------------
__global__ void ln_kernel(float* __restrict__ buf, const float* __restrict__ g,
                          const float* __restrict__ bt,
                          unsigned short* __restrict__ oh, unsigned short* __restrict__ ol,
                          int remap) {
    int row = blockIdx.x * 8 + (threadIdx.x >> 5);
    int lane = threadIdx.x & 31;
    int br = remap ? (row + 48 * (row >> 10) + 48) : row;
    float* p = buf + ((long)br) * CDIM + lane * 8;
    float4 v0 = *(float4*)p;
    float4 v1 = *(float4*)(p + 4);
    float v[8] = {v0.x, v0.y, v0.z, v0.w, v1.x, v1.y, v1.z, v1.w};
    float s = 0.0f;
#pragma unroll
    for (int i = 0; i < 8; i++) s += v[i];
#pragma unroll
    for (int o = 16; o > 0; o >>= 1) s += __shfl_xor_sync(0xffffffffu, s, o);
    float mu = s * (1.0f / 256.0f);
    float sq = 0.0f;
#pragma unroll
    for (int i = 0; i < 8; i++) { float d = v[i] - mu; sq += d * d; }
#pragma unroll
    for (int o = 16; o > 0; o >>= 1) sq += __shfl_xor_sync(0xffffffffu, sq, o);
    float rstd = rsqrtf(sq * (1.0f / 256.0f) + 1e-5f);
#pragma unroll
    for (int i = 0; i < 8; i++) {
        int c = lane * 8 + i;
        v[i] = (v[i] - mu) * rstd * g[c] + bt[c];
    }
    *(float4*)p       = make_float4(v[0], v[1], v[2], v[3]);
    *(float4*)(p + 4) = make_float4(v[4], v[5], v[6], v[7]);
    unsigned hv[4], lv[4];
#pragma unroll
    for (int i = 0; i < 8; i += 2) {
        unsigned short h0, l0, h1, l1;
        bsplit(v[i], h0, l0); bsplit(v[i + 1], h1, l1);
        hv[i >> 1] = (unsigned)h0 | ((unsigned)h1 << 16);
        lv[i >> 1] = (unsigned)l0 | ((unsigned)l1 << 16);
    }
    unsigned* ohp = (unsigned*)oh + (long)br * 128 + lane * 4;
    unsigned* olp = (unsigned*)ol + (long)br * 128 + lane * 4;
    *(uint4*)ohp = *(uint4*)hv;
    *(uint4*)olp = *(uint4*)lv;
}

// ---------------- windowed attention, online softmax, 16-token slabs ----------------
// 2 keys per iteration, 4-way split dot accumulators -> break serial FMA/MUFU chains.
__global__ void __launch_bounds__(128) attn_kernel() {
    __shared__ float sK[16 * 256];
    __shared__ float sV[16 * 256];
    int b = blockIdx.x >> 6, w = blockIdx.x & 63;
    int tid = threadIdx.x;
    int h = tid >> 4, qi = tid & 15;
    long rbase = (long)b * TGTR + w * 16;

    float q[32];
    const float* qp = g_qkv + (rbase + 48 + qi) * 768 + h * 32;
#pragma unroll
    for (int d = 0; d < 32; d++) q[d] = qp[d];

    float mx = -1e30f, sum = 0.0f;
    float o[32];
#pragma unroll
    for (int d = 0; d < 32; d++) o[d] = 0.0f;

    float4* sKf = (float4*)sK;
    float4* sVf = (float4*)sV;
    const float4* qkvf = (const float4*)g_qkv;
    const float scale = 0.17677669529663687f;   // 1/sqrt(32)

    for (int slab = 0; slab < 4; slab++) {
        __syncthreads();
#pragma unroll
        for (int i = tid; i < 1024; i += 128) {
            int jj = i >> 6, c4 = i & 63;
            long trow = rbase + slab * 16 + jj;
            sKf[i] = qkvf[trow * 192 + 64  + c4];
            sVf[i] = qkvf[trow * 192 + 128 + c4];
        }
        __syncthreads();
#pragma unroll
        for (int jj = 0; jj < 16; jj += 2) {
            const float* kp0 = sK + jj * 256 + h * 32;
            const float* kp1 = kp0 + 256;
            float a0 = 0.f, a1 = 0.f, a2 = 0.f, a3 = 0.f;
            float c0 = 0.f, c1 = 0.f, c2 = 0.f, c3 = 0.f;
#pragma unroll
            for (int d = 0; d < 32; d += 4) {
                a0 += q[d]     * kp0[d];     a1 += q[d + 1] * kp0[d + 1];
                a2 += q[d + 2] * kp0[d + 2]; a3 += q[d + 3] * kp0[d + 3];
                c0 += q[d]     * kp1[d];     c1 += q[d + 1] * kp1[d + 1];
                c2 += q[d + 2] * kp1[d + 2]; c3 += q[d + 3] * kp1[d + 3];
            }
            float s0 = ((a0 + a1) + (a2 + a3)) * scale;
            float s1 = ((c0 + c1) + (c2 + c3)) * scale;

            const float* vp0 = sV + jj * 256 + h * 32;
            const float* vp1 = vp0 + 256;

            float nm0 = fmaxf(mx, s0);
            float corr0 = __expf(mx - nm0);
            float p0 = __expf(s0 - nm0);
            sum = sum * corr0 + p0;
#pragma unroll
            for (int d = 0; d < 32; d++) o[d] = o[d] * corr0 + p0 * vp0[d];

            float nm1 = fmaxf(nm0, s1);
            float corr1 = __expf(nm0 - nm1);
            float p1 = __expf(s1 - nm1);
            sum = sum * corr1 + p1;
#pragma unroll
            for (int d = 0; d < 32; d++) o[d] = o[d] * corr1 + p1 * vp1[d];
            mx = nm1;
        }
    }
    float inv = 1.0f / sum;
    long oidx = ((long)(b * TDIM + w * 16 + qi)) * CDIM + h * 32;
    unsigned hv[16], lv[16];
#pragma unroll
    for (int d = 0; d < 32; d += 2) {
        unsigned short h0, l0, h1, l1;
        bsplit(o[d] * inv, h0, l0); bsplit(o[d + 1] * inv, h1, l1);
        hv[d >> 1] = (unsigned)h0 | ((unsigned)h1 << 16);
        lv[d >> 1] = (unsigned)l0 | ((unsigned)l1 << 16);
    }
    unsigned* ohp = (unsigned*)g_atth + (oidx >> 1);
    unsigned* olp = (unsigned*)g_attl + (oidx >> 1);
#pragma unroll
    for (int j = 0; j < 4; j++) {
        ((uint4*)ohp)[j] = ((uint4*)hv)[j];
        ((uint4*)olp)[j] = ((uint4*)lv)[j];
    }
}

// ---------------- final transpose: g_tgt[b][48+t][c] -> out[b][c][t] ----------------
__global__ void out_transpose(float* __restrict__ outp) {
    __shared__ float tile[32][33];
    int b = blockIdx.z;
    int t0 = blockIdx.x * 32, c0 = blockIdx.y * 32;
    int tx = threadIdx.x, ty = threadIdx.y;
#pragma unroll
    for (int i = 0; i < 32; i += 8)
        tile[ty + i][tx] = g_tgt[((long)(b * TGTR + CTXL + t0 + ty + i)) * CDIM + c0 + tx];
    __syncthreads();
#pragma unroll
    for (int i = 0; i < 32; i += 8)
        outp[((long)(b * CDIM + c0 + ty + i)) * TDIM + t0 + tx] = tile[tx][ty + i];
}

extern "C" void kernel_launch(void* const* d_in, const int* in_sizes, int n_in,
                              void* d_out, int out_size) {
    const float* x      = (const float*)d_in[0];
    const float* emb    = (const float*)d_in[1];
    const float* ctx_in = (const float*)d_in[2];
    const float* Wqkv   = (const float*)d_in[3];
    const float* bqkv   = (const float*)d_in[4];
    const float* Wo     = (const float*)d_in[5];
    const float* bo     = (const float*)d_in[6];
    const float* W1     = (const float*)d_in[7];
    const float* b1     = (const float*)d_in[8];
    const float* W2     = (const float*)d_in[9];
    const float* b2     = (const float*)d_in[10];
    const float* ln1g   = (const float*)d_in[11];
    const float* ln1b   = (const float*)d_in[12];
    const float* ln3g   = (const float*)d_in[13];
    const float* ln3b   = (const float*)d_in[14];

    float* outp = (float*)d_out;
    float* ctx_out = outp + (long)NB * CDIM * TDIM;
    int write_ctx = (out_size >= NB * CDIM * TDIM + NB * NLAYER * CTXL * CDIM) ? 1 : 0;

    float *tgt, *qkv, *x1;
    unsigned short *tgth, *tgtl, *atth, *attl, *x1h, *x1l, *ffh, *ffl;
    unsigned short *wqh, *wql, *woh, *wol, *w1h, *w1l, *w2h, *w2l;
    cudaGetSymbolAddress((void**)&tgt,  g_tgt);
    cudaGetSymbolAddress((void**)&qkv,  g_qkv);
    cudaGetSymbolAddress((void**)&x1,   g_x1);
    cudaGetSymbolAddress((void**)&tgth, g_tgth); cudaGetSymbolAddress((void**)&tgtl, g_tgtl);
    cudaGetSymbolAddress((void**)&atth, g_atth); cudaGetSymbolAddress((void**)&attl, g_attl);
    cudaGetSymbolAddress((void**)&x1h,  g_x1h);  cudaGetSymbolAddress((void**)&x1l,  g_x1l);
    cudaGetSymbolAddress((void**)&ffh,  g_ffh);  cudaGetSymbolAddress((void**)&ffl,  g_ffl);
    cudaGetSymbolAddress((void**)&wqh,  g_wqh);  cudaGetSymbolAddress((void**)&wql,  g_wql);
    cudaGetSymbolAddress((void**)&woh,  g_woh);  cudaGetSymbolAddress((void**)&wol,  g_wol);
    cudaGetSymbolAddress((void**)&w1h,  g_w1h);  cudaGetSymbolAddress((void**)&w1l,  g_w1l);
    cudaGetSymbolAddress((void**)&w2h,  g_w2h);  cudaGetSymbolAddress((void**)&w2l,  g_w2l);

    // weight pre-split (once per launch)
    wconv_kernel<<<512, 256>>>(Wqkv, wqh, wql, NLAYER * 3 * CDIM * CDIM);
    wconv_kernel<<<256, 256>>>(Wo,   woh, wol, NLAYER * CDIM * CDIM);
    wconv_kernel<<<512, 256>>>(W1,   w1h, w1l, NLAYER * FFD * CDIM);
    wconv_kernel<<<512, 256>>>(W2,   w2h, w2l, NLAYER * CDIM * FFD);

    conv_kernel<<<dim3(64, 16), 256>>>(x, emb);

    for (int l = 0; l < NLAYER; l++) {
        prep_kernel<<<NB, 256>>>(ctx_in, ctx_out, l, write_ctx);
        // QKV: M=17152, N=768, K=256 -> qkv f32
        gemm_kernel<0><<<dim3(6, 134), 256>>>(
            (unsigned*)tgth, (unsigned*)tgtl,
            (unsigned*)(wqh + (long)l * 3 * CDIM * CDIM), (unsigned*)(wql + (long)l * 3 * CDIM * CDIM),
            bqkv + l * 768, nullptr, qkv, nullptr, nullptr, 256, 768, 0, 0);
        attn_kernel<<<NB * 64, 128>>>();
        // Wo: M=16384, N=256, K=256, +res(tgt remap) -> x1 f32
        gemm_kernel<1><<<dim3(2, 128), 256>>>(
            (unsigned*)atth, (unsigned*)attl,
            (unsigned*)(woh + (long)l * CDIM * CDIM), (unsigned*)(wol + (long)l * CDIM * CDIM),
            bo + l * 256, tgt, x1, nullptr, nullptr, 256, 256, 1, 0);
        ln_kernel<<<2048, 256>>>(x1, ln1g + l * 256, ln1b + l * 256, x1h, x1l, 0);
        // FF1: M=16384, N=1024, K=256, relu -> ff hi/lo
        gemm_kernel<2><<<dim3(8, 128), 256>>>(
            (unsigned*)x1h, (unsigned*)x1l,
            (unsigned*)(w1h + (long)l * FFD * CDIM), (unsigned*)(w1l + (long)l * FFD * CDIM),
            b1 + l * 1024, nullptr, nullptr, ffh, ffl, 256, 1024, 0, 0);
        // FF2: M=16384, N=256, K=1024, +res(x1) -> tgt f32 (remap rows)
        gemm_kernel<1><<<dim3(2, 128), 256>>>(
            (unsigned*)ffh, (unsigned*)ffl,
            (unsigned*)(w2h + (long)l * CDIM * FFD), (unsigned*)(w2l + (long)l * CDIM * FFD),
            b2 + l * 256, x1, tgt, nullptr, nullptr, 1024, 256, 0, 1);
        ln_kernel<<<2048, 256>>>(tgt, ln3g + l * 256, ln3b + l * 256, tgth, tgtl, 1);
    }

    out_transpose<<<dim3(32, 8, 16), dim3(32, 8)>>>(outp);
}

// round 16
// speedup vs baseline: 1.1151x; 1.0308x over previous
#include <cuda_runtime.h>
#include <cuda_bf16.h>
#include <math.h>
#include <stdint.h>

#define NB 16
#define CDIM 256
#define TDIM 1024
#define CTXL 48
#define TGTR 1072      // CTXL + TDIM
#define FFD 1024
#define NLAYER 4
#define MQ (NB * TGTR)   // 17152
#define MT (NB * TDIM)   // 16384

// ---------------- scratch (static device globals — no allocation) ----------------
__device__ float g_tgt[MQ * CDIM];
__device__ float g_qkv[MQ * 3 * CDIM];
__device__ float g_x1 [MT * CDIM];

__device__ unsigned short g_tgth[MQ * CDIM], g_tgtl[MQ * CDIM];
__device__ unsigned short g_atth[MT * CDIM], g_attl[MT * CDIM];
__device__ unsigned short g_x1h [MT * CDIM], g_x1l [MT * CDIM];
__device__ unsigned short g_ffh [MT * FFD],  g_ffl [MT * FFD];

__device__ unsigned short g_wqh[NLAYER*3*CDIM*CDIM], g_wql[NLAYER*3*CDIM*CDIM];
__device__ unsigned short g_woh[NLAYER*CDIM*CDIM],   g_wol[NLAYER*CDIM*CDIM];
__device__ unsigned short g_w1h[NLAYER*FFD*CDIM],    g_w1l[NLAYER*FFD*CDIM];
__device__ unsigned short g_w2h[NLAYER*CDIM*FFD],    g_w2l[NLAYER*CDIM*FFD];

// ---------------- helpers ----------------
__device__ __forceinline__ void bsplit(float x, unsigned short& h, unsigned short& l) {
    __nv_bfloat16 hb = __float2bfloat16(x);
    float r = x - __bfloat162float(hb);
    __nv_bfloat16 lb = __float2bfloat16(r);
    h = *(unsigned short*)&hb; l = *(unsigned short*)&lb;
}

__device__ __forceinline__ void mma16816(float* d, const unsigned* a, unsigned b0, unsigned b1) {
    asm volatile(
        "mma.sync.aligned.m16n8k16.row.col.f32.bf16.bf16.f32 "
        "{%0,%1,%2,%3}, {%4,%5,%6,%7}, {%8,%9}, {%0,%1,%2,%3};"
        : "+f"(d[0]), "+f"(d[1]), "+f"(d[2]), "+f"(d[3])
        : "r"(a[0]), "r"(a[1]), "r"(a[2]), "r"(a[3]), "r"(b0), "r"(b1));
}

// ---------------- depthwise causal conv (Le=32), fused bf16 split ----------------
__global__ void conv_kernel(const float* __restrict__ x, const float* __restrict__ emb) {
    int b = blockIdx.y;
    int t0 = blockIdx.x * 16;
    int c = threadIdx.x;
    float f[32];
#pragma unroll
    for (int l = 0; l < 32; l++)
        f[l] = 0.5f * (emb[((b * 2 + 0) * CDIM + c) * 32 + l] +
                       emb[((b * 2 + 1) * CDIM + c) * 32 + l]);
    float xv[47];
    const float* xr = x + ((long)(b * CDIM + c)) * TDIM;
#pragma unroll
    for (int l = 0; l < 47; l++) {
        int t = t0 - 31 + l;
        xv[l] = (t >= 0) ? xr[t] : 0.0f;
    }
#pragma unroll
    for (int tt = 0; tt < 16; tt++) {
        float s = 0.0f;
#pragma unroll
        for (int l = 0; l < 32; l++) s += xv[tt + l] * f[l];
        long idx = ((long)(b * TGTR + CTXL + t0 + tt)) * CDIM + c;
        g_tgt[idx] = s;
        unsigned short h, lo; bsplit(s, h, lo);
        g_tgth[idx] = h; g_tgtl[idx] = lo;
    }
}

// ---------------- per-layer prep: ctx snapshot + ctx load (+ split) ----------------
__global__ void prep_kernel(const float* __restrict__ ctx_in, float* __restrict__ ctx_out,
                            int layer, int write_ctx) {
    int b = blockIdx.x;
    long snap_base = ((long)(b * TGTR + TDIM)) * CDIM;
    long tgt_base  = ((long)(b * TGTR)) * CDIM;
    long io_base   = ((long)((b * NLAYER + layer) * CTXL)) * CDIM;
    for (int i = threadIdx.x; i < CTXL * CDIM; i += blockDim.x) {
        if (write_ctx) ctx_out[io_base + i] = g_tgt[snap_base + i];
        float v = ctx_in[io_base + i];
        g_tgt[tgt_base + i] = v;
        unsigned short h, lo; bsplit(v, h, lo);
        g_tgth[tgt_base + i] = h; g_tgtl[tgt_base + i] = lo;
    }
}

// ---------------- all weight fp32 -> bf16 hi/lo in ONE launch ----------------
__global__ void wconv_all(const float* __restrict__ wq, const float* __restrict__ wo,
                          const float* __restrict__ w1, const float* __restrict__ w2) {
    int stride = gridDim.x * blockDim.x;
    int tid0 = blockIdx.x * blockDim.x + threadIdx.x;
    const int nq = NLAYER * 3 * CDIM * CDIM;
    const int no = NLAYER * CDIM * CDIM;
    const int n1 = NLAYER * FFD * CDIM;
    const int n2 = NLAYER * CDIM * FFD;
    for (int i = tid0; i < nq; i += stride) {
        unsigned short hh, ll; bsplit(wq[i], hh, ll);
        g_wqh[i] = hh; g_wql[i] = ll;
    }
    for (int i = tid0; i < no; i += stride) {
        unsigned short hh, ll; bsplit(wo[i], hh, ll);
        g_woh[i] = hh; g_wol[i] = ll;
    }
    for (int i = tid0; i < n1; i += stride) {
        unsigned short hh, ll; bsplit(w1[i], hh, ll);
        g_w1h[i] = hh; g_w1l[i] = ll;
    }
    for (int i = tid0; i < n2; i += stride) {
        unsigned short hh, ll; bsplit(w2[i], hh, ll);
        g_w2h[i] = hh; g_w2l[i] = ll;
    }
}

// ---------------- GEMM via mma.sync bf16 3-split, pre-split operands (R11 design) ----
// out[M,N] = A[M,K] @ W[N,K]^T + bias.
// EPI: 0 = +bias -> f32 ; 1 = +bias + res -> f32 ; 2 = +bias, relu -> bf16 hi/lo
// A,W given as u32 arrays of packed bf16 pairs: [row][K/2].
// Block 128x128, 8 warps (4m x 2n), warp tile 32x64, k-step 16.
template<int EPI>
__global__ void __launch_bounds__(256, 2) gemm_kernel(
    const unsigned* __restrict__ Ah, const unsigned* __restrict__ Al,
    const unsigned* __restrict__ Wh, const unsigned* __restrict__ Wl,
    const float* __restrict__ bias, const float* __restrict__ res,
    float* __restrict__ outf, unsigned short* __restrict__ outh, unsigned short* __restrict__ outl,
    int K, int N, int res_remap, int out_remap)
{
    __shared__ unsigned sA[2][128][12];   // [hi/lo][row][8 u32 used, stride 12]
    __shared__ unsigned sB[2][128][12];

    int tid = threadIdx.x;
    int lane = tid & 31;
    int wid = tid >> 5;
    int wm = wid >> 1;
    int wn = wid & 1;
    int g = lane >> 2, t = lane & 3;
    int m0 = blockIdx.y * 128, n0 = blockIdx.x * 128;

    float acc[2][8][4];
#pragma unroll
    for (int i = 0; i < 2; i++)
#pragma unroll
        for (int j = 0; j < 8; j++)
#pragma unroll
            for (int c = 0; c < 4; c++) acc[i][j][c] = 0.0f;

    int Ku = K >> 1;
    int srow = tid >> 1;            // 0..127
    int uc   = (tid & 1) * 4;       // u32 col 0..3 or 4..7
    const unsigned* Aph = Ah + (long)(m0 + srow) * Ku + uc;
    const unsigned* Apl = Al + (long)(m0 + srow) * Ku + uc;
    const unsigned* Wph = Wh + (long)(n0 + srow) * Ku + uc;
    const unsigned* Wpl = Wl + (long)(n0 + srow) * Ku + uc;

    uint4 ah4 = *(const uint4*)Aph;
    uint4 al4 = *(const uint4*)Apl;
    uint4 wh4 = *(const uint4*)Wph;
    uint4 wl4 = *(const uint4*)Wpl;

    int KT = K >> 4;
    for (int kt = 0; kt < KT; kt++) {
        // stage current k-tile (pure copies)
        sA[0][srow][uc + 0] = ah4.x; sA[0][srow][uc + 1] = ah4.y;
        sA[0][srow][uc + 2] = ah4.z; sA[0][srow][uc + 3] = ah4.w;
        sA[1][srow][uc + 0] = al4.x; sA[1][srow][uc + 1] = al4.y;
        sA[1][srow][uc + 2] = al4.z; sA[1][srow][uc + 3] = al4.w;
        sB[0][srow][uc + 0] = wh4.x; sB[0][srow][uc + 1] = wh4.y;
        sB[0][srow][uc + 2] = wh4.z; sB[0][srow][uc + 3] = wh4.w;
        sB[1][srow][uc + 0] = wl4.x; sB[1][srow][uc + 1] = wl4.y;
        sB[1][srow][uc + 2] = wl4.z; sB[1][srow][uc + 3] = wl4.w;
        __syncthreads();

        bool more = (kt + 1 < KT);
        if (more) {
            int off = (kt + 1) << 3;
            ah4 = *(const uint4*)(Aph + off);
            al4 = *(const uint4*)(Apl + off);
            wh4 = *(const uint4*)(Wph + off);
            wl4 = *(const uint4*)(Wpl + off);
        }

        unsigned afh[2][4], afl[2][4];
#pragma unroll
        for (int tm = 0; tm < 2; tm++) {
            int r = wm * 32 + tm * 16 + g;
            afh[tm][0] = sA[0][r][t];     afh[tm][1] = sA[0][r + 8][t];
            afh[tm][2] = sA[0][r][4 + t]; afh[tm][3] = sA[0][r + 8][4 + t];
            afl[tm][0] = sA[1][r][t];     afl[tm][1] = sA[1][r + 8][t];
            afl[tm][2] = sA[1][r][4 + t]; afl[tm][3] = sA[1][r + 8][4 + t];
        }
#pragma unroll
        for (int tn = 0; tn < 8; tn++) {
            int nc = wn * 64 + tn * 8 + g;
            unsigned b0h = sB[0][nc][t], b1h = sB[0][nc][4 + t];
            unsigned b0l = sB[1][nc][t], b1l = sB[1][nc][4 + t];
#pragma unroll
            for (int tm = 0; tm < 2; tm++) {
                mma16816(acc[tm][tn], afh[tm], b0h, b1h);   // hi*hi
                mma16816(acc[tm][tn], afl[tm], b0h, b1h);   // lo*hi
                mma16816(acc[tm][tn], afh[tm], b0l, b1l);   // hi*lo
            }
        }
        __syncthreads();
    }

    // epilogue: c0=(g,2t) c1=(g,2t+1) c2=(g+8,2t) c3=(g+8,2t+1)
#pragma unroll
    for (int tm = 0; tm < 2; tm++) {
#pragma unroll
        for (int tn = 0; tn < 8; tn++) {
            int col = n0 + wn * 64 + tn * 8 + 2 * t;
            float bz0 = bias[col], bz1 = bias[col + 1];
#pragma unroll
            for (int half = 0; half < 2; half++) {
                int row = m0 + wm * 32 + tm * 16 + g + half * 8;
                float v0 = acc[tm][tn][half * 2 + 0] + bz0;
                float v1 = acc[tm][tn][half * 2 + 1] + bz1;
                if (EPI == 1) {
                    long rrow = res_remap ? (row + 48 * (row >> 10) + 48) : row;
                    const float* rp = &res[rrow * CDIM + col];
                    v0 += rp[0]; v1 += rp[1];
                }
                if (EPI == 2) {
                    v0 = fmaxf(v0, 0.0f); v1 = fmaxf(v1, 0.0f);
                    unsigned short h0, l0, h1, l1;
                    bsplit(v0, h0, l0); bsplit(v1, h1, l1);
                    long oi = (long)row * (N >> 1) + (col >> 1);
                    ((unsigned*)outh)[oi] = (unsigned)h0 | ((unsigned)h1 << 16);
                    ((unsigned*)outl)[oi] = (unsigned)l0 | ((unsigned)l1 << 16);
                } else {
                    long orow = out_remap ? (row + 48 * (row >> 10) + 48) : row;
                    *(float2*)&outf[orow * (long)N + col] = make_float2(v0, v1);
                }
            }
        }
    }
}

// ---------------- LayerNorm (in place) + bf16 split ----------------
__global__ void ln_kernel(float* __restrict__ buf, const float* __restrict__ g,
                          const float* __restrict__ bt,
                          unsigned short* __restrict__ oh, unsigned short* __restrict__ ol,
                          int remap) {
    int row = blockIdx.x * 8 + (threadIdx.x >> 5);
    int lane = threadIdx.x & 31;
    int br = remap ? (row + 48 * (row >> 10) + 48) : row;
    float* p = buf + ((long)br) * CDIM + lane * 8;
    float4 v0 = *(float4*)p;
    float4 v1 = *(float4*)(p + 4);
    float v[8] = {v0.x, v0.y, v0.z, v0.w, v1.x, v1.y, v1.z, v1.w};
    float s = 0.0f;
#pragma unroll
    for (int i = 0; i < 8; i++) s += v[i];
#pragma unroll
    for (int o = 16; o > 0; o >>= 1) s += __shfl_xor_sync(0xffffffffu, s, o);
    float mu = s * (1.0f / 256.0f);
    float sq = 0.0f;
#pragma unroll
    for (int i = 0; i < 8; i++) { float d = v[i] - mu; sq += d * d; }
#pragma unroll
    for (int o = 16; o > 0; o >>= 1) sq += __shfl_xor_sync(0xffffffffu, sq, o);
    float rstd = rsqrtf(sq * (1.0f / 256.0f) + 1e-5f);
#pragma unroll
    for (int i = 0; i < 8; i++) {
        int c = lane * 8 + i;
        v[i] = (v[i] - mu) * rstd * g[c] + bt[c];
    }
    *(float4*)p       = make_float4(v[0], v[1], v[2], v[3]);
    *(float4*)(p + 4) = make_float4(v[4], v[5], v[6], v[7]);
    unsigned hv[4], lv[4];
#pragma unroll
    for (int i = 0; i < 8; i += 2) {
        unsigned short h0, l0, h1, l1;
        bsplit(v[i], h0, l0); bsplit(v[i + 1], h1, l1);
        hv[i >> 1] = (unsigned)h0 | ((unsigned)h1 << 16);
        lv[i >> 1] = (unsigned)l0 | ((unsigned)l1 << 16);
    }
    unsigned* ohp = (unsigned*)oh + (long)br * 128 + lane * 4;
    unsigned* olp = (unsigned*)ol + (long)br * 128 + lane * 4;
    *(uint4*)ohp = *(uint4*)hv;
    *(uint4*)olp = *(uint4*)lv;
}

// ---------------- windowed attention, dim-split threads ----------------
// Block 256 thr: warp = one head; lane = qi*2 + half; thread owns 16 of 32 dims.
// Score = own 16-dim partial + shfl_xor(partial, 1). Online softmax per thread
// (redundant across the half-pair, identical values).
__global__ void __launch_bounds__(256, 3) attn_kernel() {
    __shared__ float sK[16 * 256];
    __shared__ float sV[16 * 256];
    int b = blockIdx.x >> 6, w = blockIdx.x & 63;
    int tid = threadIdx.x;
    int half = tid & 1, qi = (tid >> 1) & 15, h = tid >> 5;
    long rbase = (long)b * TGTR + w * 16;

    float q[16];
    const float* qp = g_qkv + (rbase + 48 + qi) * 768 + h * 32 + half * 16;
#pragma unroll
    for (int d = 0; d < 16; d++) q[d] = qp[d];

    float mx = -1e30f, sum = 0.0f;
    float o[16];
#pragma unroll
    for (int d = 0; d < 16; d++) o[d] = 0.0f;

    float4* sKf = (float4*)sK;
    float4* sVf = (float4*)sV;
    const float4* qkvf = (const float4*)g_qkv;
    const float scale = 0.17677669529663687f;   // 1/sqrt(32)

    for (int slab = 0; slab < 4; slab++) {
        __syncthreads();
#pragma unroll
        for (int i = tid; i < 1024; i += 256) {
            int jj = i >> 6, c4 = i & 63;
            long trow = rbase + slab * 16 + jj;
            sKf[i] = qkvf[trow * 192 + 64  + c4];
            sVf[i] = qkvf[trow * 192 + 128 + c4];
        }
        __syncthreads();
#pragma unroll
        for (int jj = 0; jj < 16; jj++) {
            const float* kp = sK + jj * 256 + h * 32 + half * 16;
            float part = 0.0f;
#pragma unroll
            for (int d = 0; d < 16; d++) part += q[d] * kp[d];
            float s = (part + __shfl_xor_sync(0xffffffffu, part, 1)) * scale;
            float nm = fmaxf(mx, s);
            float corr = __expf(mx - nm);
            float p = __expf(s - nm);
            sum = sum * corr + p;
            const float* vp = sV + jj * 256 + h * 32 + half * 16;
#pragma unroll
            for (int d = 0; d < 16; d++) o[d] = o[d] * corr + p * vp[d];
            mx = nm;
        }
    }
    float inv = 1.0f / sum;
    long oidx = ((long)(b * TDIM + w * 16 + qi)) * CDIM + h * 32 + half * 16;
    unsigned hv[8], lv[8];
#pragma unroll
    for (int d = 0; d < 16; d += 2) {
        unsigned short h0, l0, h1, l1;
        bsplit(o[d] * inv, h0, l0); bsplit(o[d + 1] * inv, h1, l1);
        hv[d >> 1] = (unsigned)h0 | ((unsigned)h1 << 16);
        lv[d >> 1] = (unsigned)l0 | ((unsigned)l1 << 16);
    }
    unsigned* ohp = (unsigned*)g_atth + (oidx >> 1);
    unsigned* olp = (unsigned*)g_attl + (oidx >> 1);
    ((uint4*)ohp)[0] = ((uint4*)hv)[0];
    ((uint4*)ohp)[1] = ((uint4*)hv)[1];
    ((uint4*)olp)[0] = ((uint4*)lv)[0];
    ((uint4*)olp)[1] = ((uint4*)lv)[1];
}

// ---------------- final transpose: g_tgt[b][48+t][c] -> out[b][c][t] ----------------
__global__ void out_transpose(float* __restrict__ outp) {
    __shared__ float tile[32][33];
    int b = blockIdx.z;
    int t0 = blockIdx.x * 32, c0 = blockIdx.y * 32;
    int tx = threadIdx.x, ty = threadIdx.y;
#pragma unroll
    for (int i = 0; i < 32; i += 8)
        tile[ty + i][tx] = g_tgt[((long)(b * TGTR + CTXL + t0 + ty + i)) * CDIM + c0 + tx];
    __syncthreads();
#pragma unroll
    for (int i = 0; i < 32; i += 8)
        outp[((long)(b * CDIM + c0 + ty + i)) * TDIM + t0 + tx] = tile[tx][ty + i];
}

extern "C" void kernel_launch(void* const* d_in, const int* in_sizes, int n_in,
                              void* d_out, int out_size) {
    const float* x      = (const float*)d_in[0];
    const float* emb    = (const float*)d_in[1];
    const float* ctx_in = (const float*)d_in[2];
    const float* Wqkv   = (const float*)d_in[3];
    const float* bqkv   = (const float*)d_in[4];
    const float* Wo     = (const float*)d_in[5];
    const float* bo     = (const float*)d_in[6];
    const float* W1     = (const float*)d_in[7];
    const float* b1     = (const float*)d_in[8];
    const float* W2     = (const float*)d_in[9];
    const float* b2     = (const float*)d_in[10];
    const float* ln1g   = (const float*)d_in[11];
    const float* ln1b   = (const float*)d_in[12];
    const float* ln3g   = (const float*)d_in[13];
    const float* ln3b   = (const float*)d_in[14];

    float* outp = (float*)d_out;
    float* ctx_out = outp + (long)NB * CDIM * TDIM;
    int write_ctx = (out_size >= NB * CDIM * TDIM + NB * NLAYER * CTXL * CDIM) ? 1 : 0;

    float *tgt, *qkv, *x1;
    unsigned short *tgth, *tgtl, *atth, *attl, *x1h, *x1l, *ffh, *ffl;
    unsigned short *wqh, *wql, *woh, *wol, *w1h, *w1l, *w2h, *w2l;
    cudaGetSymbolAddress((void**)&tgt,  g_tgt);
    cudaGetSymbolAddress((void**)&qkv,  g_qkv);
    cudaGetSymbolAddress((void**)&x1,   g_x1);
    cudaGetSymbolAddress((void**)&tgth, g_tgth); cudaGetSymbolAddress((void**)&tgtl, g_tgtl);
    cudaGetSymbolAddress((void**)&atth, g_atth); cudaGetSymbolAddress((void**)&attl, g_attl);
    cudaGetSymbolAddress((void**)&x1h,  g_x1h);  cudaGetSymbolAddress((void**)&x1l,  g_x1l);
    cudaGetSymbolAddress((void**)&ffh,  g_ffh);  cudaGetSymbolAddress((void**)&ffl,  g_ffl);
    cudaGetSymbolAddress((void**)&wqh,  g_wqh);  cudaGetSymbolAddress((void**)&wql,  g_wql);
    cudaGetSymbolAddress((void**)&woh,  g_woh);  cudaGetSymbolAddress((void**)&wol,  g_wol);
    cudaGetSymbolAddress((void**)&w1h,  g_w1h);  cudaGetSymbolAddress((void**)&w1l,  g_w1l);
    cudaGetSymbolAddress((void**)&w2h,  g_w2h);  cudaGetSymbolAddress((void**)&w2l,  g_w2l);

    // weight pre-split, single launch
    wconv_all<<<1024, 256>>>(Wqkv, Wo, W1, W2);

    conv_kernel<<<dim3(64, 16), 256>>>(x, emb);

    for (int l = 0; l < NLAYER; l++) {
        prep_kernel<<<NB, 256>>>(ctx_in, ctx_out, l, write_ctx);
        // QKV: M=17152, N=768, K=256 -> qkv f32
        gemm_kernel<0><<<dim3(6, 134), 256>>>(
            (unsigned*)tgth, (unsigned*)tgtl,
            (unsigned*)(wqh + (long)l * 3 * CDIM * CDIM), (unsigned*)(wql + (long)l * 3 * CDIM * CDIM),
            bqkv + l * 768, nullptr, qkv, nullptr, nullptr, 256, 768, 0, 0);
        attn_kernel<<<NB * 64, 256>>>();
        // Wo: M=16384, N=256, K=256, +res(tgt remap) -> x1 f32
        gemm_kernel<1><<<dim3(2, 128), 256>>>(
            (unsigned*)atth, (unsigned*)attl,
            (unsigned*)(woh + (long)l * CDIM * CDIM), (unsigned*)(wol + (long)l * CDIM * CDIM),
            bo + l * 256, tgt, x1, nullptr, nullptr, 256, 256, 1, 0);
        ln_kernel<<<2048, 256>>>(x1, ln1g + l * 256, ln1b + l * 256, x1h, x1l, 0);
        // FF1: M=16384, N=1024, K=256, relu -> ff hi/lo
        gemm_kernel<2><<<dim3(8, 128), 256>>>(
            (unsigned*)x1h, (unsigned*)x1l,
            (unsigned*)(w1h + (long)l * FFD * CDIM), (unsigned*)(w1l + (long)l * FFD * CDIM),
            b1 + l * 1024, nullptr, nullptr, ffh, ffl, 256, 1024, 0, 0);
        // FF2: M=16384, N=256, K=1024, +res(x1) -> tgt f32 (remap rows)
        gemm_kernel<1><<<dim3(2, 128), 256>>>(
            (unsigned*)ffh, (unsigned*)ffl,
            (unsigned*)(w2h + (long)l * CDIM * FFD), (unsigned*)(w2l + (long)l * CDIM * FFD),
            b2 + l * 256, x1, tgt, nullptr, nullptr, 1024, 256, 0, 1);
        ln_kernel<<<2048, 256>>>(tgt, ln3g + l * 256, ln3b + l * 256, tgth, tgtl, 1);
    }

    out_transpose<<<dim3(32, 8, 16), dim3(32, 8)>>>(outp);
}